// round 2
// baseline (speedup 1.0000x reference)
#include <cuda_runtime.h>
#include <cstdint>

// Problem constants (fixed by the reference).
#define BTOT 4096
#define T    200
#define D    64
#define H1D  80
#define H2D  40
#define TP   201   // padded T stride: 201 mod 32 = 9 -> conflict-free column access

#define NEG_BIG (-2147483648.0f)   // -2^31 as float

// Shared memory layout (floats)
#define SM_FLOATS (64*TP + 80*TP + 40*TP + 64*80 + 80*40 + 64 + 80 + 40 + 40 + 200 + 288)
#define SM_BYTES  (SM_FLOATS * 4)

__device__ __forceinline__ float fsigmoid(float x) {
    return __fdividef(1.0f, 1.0f + __expf(-x));
}

// ---- packed f32x2 helpers (Blackwell: fma.rn.f32x2 doubles fp32 FMA rate) ----
__device__ __forceinline__ unsigned long long pk2(float lo, float hi) {
    unsigned long long r;
    asm("mov.b64 %0, {%1, %2};"
        : "=l"(r) : "r"(__float_as_uint(lo)), "r"(__float_as_uint(hi)));
    return r;
}
__device__ __forceinline__ void upk2(unsigned long long v, float& lo, float& hi) {
    unsigned int a, b;
    asm("mov.b64 {%0, %1}, %2;" : "=r"(a), "=r"(b) : "l"(v));
    lo = __uint_as_float(a);
    hi = __uint_as_float(b);
}
__device__ __forceinline__ void fma2(unsigned long long& d,
                                     unsigned long long a, unsigned long long b) {
    asm("fma.rn.f32x2 %0, %1, %2, %3;" : "=l"(d) : "l"(a), "l"(b), "l"(d));
}

__global__ __launch_bounds__(256, 1)
void attn_layer_kernel(const float* __restrict__ query,
                       const float* __restrict__ fact,
                       const int*   __restrict__ mask,
                       const float* __restrict__ W1,
                       const float* __restrict__ b1,
                       const float* __restrict__ W2,
                       const float* __restrict__ b2,
                       const float* __restrict__ W3,
                       const float* __restrict__ b3,
                       float* __restrict__ out)
{
    extern __shared__ float sm[];
    float* f_t = sm;                    // [64][TP]
    float* h1t = f_t + 64 * TP;         // [80][TP]
    float* h2t = h1t + 80 * TP;         // [40][TP]
    float* Wb  = h2t + 40 * TP;         // [64][80]
    float* W2s = Wb  + 64 * 80;         // [80][40]
    float* qs  = W2s + 80 * 40;         // [64]
    float* bb  = qs  + 64;              // [80]
    float* b2s = bb  + 80;              // [40]
    float* W3s = b2s + 40;              // [40]
    float* wts = W3s + 40;              // [200]
    float* red = wts + 200;             // [288]

    const int b    = blockIdx.x;
    const int tid  = threadIdx.x;
    const int lane = tid & 31;
    const int wid  = tid >> 5;

    // ---- Prefetch long-latency scalars early (hide LDG latency) ----
    int   my_mask = 0;
    if (tid < T) my_mask = mask[(size_t)b * T + tid];
    const float b3v = b3[0];

    // ---- Stage 0: load q + small constants ----
    if (tid < D) qs[tid] = query[b * D + tid];
    if (tid >= 64 && tid < 64 + H2D) {
        int k = tid - 64;
        b2s[k] = b2[k];
        W3s[k] = W3[k];
    }
    for (int i = tid; i < H1D * H2D; i += 256) W2s[i] = W2[i];
    __syncthreads();   // qs ready for Wb/bias build

    // ---- Stage 1: load fact (transposed) + build per-batch Wb, bias ----
    const float* fb = fact + (size_t)b * T * D;
    for (int e = tid; e < T * D; e += 256) {
        int t = e >> 6, d = e & 63;
        f_t[d * TP + t] = fb[e];
    }
    // Wb[d][h] = W1a[d][h] - W1d[d][h] + q[d]*W1c[d][h]
    for (int e = tid; e < D * H1D; e += 256) {
        int d = e / H1D, h = e - d * H1D;
        float a  = W1[d * H1D + h];            // fact block
        float cc = W1[(128 + d) * H1D + h];    // f*q block
        float dd = W1[(192 + d) * H1D + h];    // (q-f) block
        Wb[e] = (a - dd) + qs[d] * cc;
    }
    // bb[h] = b1[h] + sum_d q[d]*(W1b[d][h] + W1d[d][h])
    if (tid < H1D) {
        float s = b1[tid];
        #pragma unroll 8
        for (int d = 0; d < D; d++) {
            s += qs[d] * (W1[(64 + d) * H1D + tid] + W1[(192 + d) * H1D + tid]);
        }
        bb[tid] = s;
    }
    __syncthreads();

    // ---- Stage 2: GEMM1  h1[t][h] = sigmoid(f[t,:] @ Wb[:,h] + bb[h]) ----
    // 250 thread-tiles of 8t x 8h: t = tg + 25*i (i<8), h = hg + 10*j (j<8)
    // f32x2: accumulator pairs along t -> acc2[p][j] holds {t=tg+50p, t=tg+50p+25}
    if (tid < 250) {
        const int tg = tid / 10;   // 0..24
        const int hg = tid % 10;   // 0..9
        unsigned long long acc2[4][8];
        const unsigned long long z = pk2(0.0f, 0.0f);
        #pragma unroll
        for (int p = 0; p < 4; p++)
            #pragma unroll
            for (int j = 0; j < 8; j++) acc2[p][j] = z;

        #pragma unroll 4
        for (int d = 0; d < D; d++) {
            float rf[8];
            #pragma unroll
            for (int i = 0; i < 8; i++) rf[i] = f_t[d * TP + tg + 25 * i];
            unsigned long long rf2[4];
            #pragma unroll
            for (int p = 0; p < 4; p++) rf2[p] = pk2(rf[2 * p], rf[2 * p + 1]);
            #pragma unroll
            for (int j = 0; j < 8; j++) {
                float w = Wb[d * H1D + hg + 10 * j];
                unsigned long long w2 = pk2(w, w);
                #pragma unroll
                for (int p = 0; p < 4; p++) fma2(acc2[p][j], rf2[p], w2);
            }
        }
        #pragma unroll
        for (int j = 0; j < 8; j++) {
            const int h = hg + 10 * j;
            const float bias = bb[h];
            #pragma unroll
            for (int p = 0; p < 4; p++) {
                float a0, a1;
                upk2(acc2[p][j], a0, a1);
                const int t0 = tg + 50 * p;       // i = 2p
                const int t1 = tg + 50 * p + 25;  // i = 2p+1
                h1t[h * TP + t0] = fsigmoid(a0 + bias);
                h1t[h * TP + t1] = fsigmoid(a1 + bias);
            }
        }
    }
    __syncthreads();

    // ---- Stage 3: GEMM2  h2[t][k] = sigmoid(h1[t,:] @ W2[:,k] + b2[k]) ----
    // 250 thread-tiles of 8t x 4k, f32x2 pairs along t
    if (tid < 250) {
        const int tg = tid / 10;   // 0..24
        const int kg = tid % 10;   // 0..9
        unsigned long long acc2[4][4];
        const unsigned long long z = pk2(0.0f, 0.0f);
        #pragma unroll
        for (int p = 0; p < 4; p++)
            #pragma unroll
            for (int j = 0; j < 4; j++) acc2[p][j] = z;

        #pragma unroll 4
        for (int h = 0; h < H1D; h++) {
            float rh[8];
            #pragma unroll
            for (int i = 0; i < 8; i++) rh[i] = h1t[h * TP + tg + 25 * i];
            unsigned long long rh2[4];
            #pragma unroll
            for (int p = 0; p < 4; p++) rh2[p] = pk2(rh[2 * p], rh[2 * p + 1]);
            #pragma unroll
            for (int j = 0; j < 4; j++) {
                float w = W2s[h * H2D + kg + 10 * j];
                unsigned long long w2 = pk2(w, w);
                #pragma unroll
                for (int p = 0; p < 4; p++) fma2(acc2[p][j], rh2[p], w2);
            }
        }
        #pragma unroll
        for (int j = 0; j < 4; j++) {
            const int k = kg + 10 * j;
            const float bias = b2s[k];
            #pragma unroll
            for (int p = 0; p < 4; p++) {
                float a0, a1;
                upk2(acc2[p][j], a0, a1);
                const int t0 = tg + 50 * p;
                const int t1 = tg + 50 * p + 25;
                h2t[k * TP + t0] = fsigmoid(a0 + bias);
                h2t[k * TP + t1] = fsigmoid(a1 + bias);
            }
        }
    }
    __syncthreads();

    // ---- Stage 4: scores + masked softmax ----
    float sc = NEG_BIG;
    float maskf = 0.0f;
    if (tid < T) {
        float s = b3v;
        #pragma unroll 8
        for (int k = 0; k < H2D; k++)
            s = fmaf(h2t[k * TP + tid], W3s[k], s);
        maskf = (float)my_mask;
        sc = (my_mask == 1) ? s : NEG_BIG;
    }
    // block max
    float m = sc;
    #pragma unroll
    for (int o = 16; o; o >>= 1) m = fmaxf(m, __shfl_xor_sync(0xffffffffu, m, o));
    if (lane == 0) red[wid] = m;
    __syncthreads();
    if (tid == 0) {
        float mm = red[0];
        #pragma unroll
        for (int i = 1; i < 8; i++) mm = fmaxf(mm, red[i]);
        red[256] = mm;
    }
    __syncthreads();
    const float rowmax = red[256];

    float e = 0.0f;
    if (tid < T) e = __expf(sc - rowmax);   // masked -> exp(-huge) = 0
    float s2 = e;
    #pragma unroll
    for (int o = 16; o; o >>= 1) s2 += __shfl_xor_sync(0xffffffffu, s2, o);
    if (lane == 0) red[wid] = s2;
    __syncthreads();
    if (tid == 0) {
        float ss = 0.0f;
        #pragma unroll
        for (int i = 0; i < 8; i++) ss += red[i];
        red[257] = ss;
    }
    __syncthreads();
    const float inv_sum = __fdividef(1.0f, red[257]);
    if (tid < T) wts[tid] = e * maskf * inv_sum;
    __syncthreads();

    // ---- Stage 5: out[b][d] = sum_t wts[t] * fact[t][d] ----
    {
        const int d = tid & 63;
        const int c = tid >> 6;      // 4 chunks of 50 t
        float s = 0.0f;
        const int t0 = c * 50;
        #pragma unroll 10
        for (int t = t0; t < t0 + 50; t++)
            s = fmaf(wts[t], f_t[d * TP + t], s);
        red[c * 64 + d] = s;
    }
    __syncthreads();
    if (tid < D) {
        out[(size_t)b * D + tid] = red[tid] + red[64 + tid] + red[128 + tid] + red[192 + tid];
    }
}

extern "C" void kernel_launch(void* const* d_in, const int* in_sizes, int n_in,
                              void* d_out, int out_size)
{
    const float* query = (const float*)d_in[0];
    const float* fact  = (const float*)d_in[1];
    const int*   mask  = (const int*)  d_in[2];
    const float* W1    = (const float*)d_in[3];
    const float* b1    = (const float*)d_in[4];
    const float* W2    = (const float*)d_in[5];
    const float* b2    = (const float*)d_in[6];
    const float* W3    = (const float*)d_in[7];
    const float* b3    = (const float*)d_in[8];
    float* out = (float*)d_out;

    const int nb = in_sizes[0] / D;    // = B

    cudaFuncSetAttribute(attn_layer_kernel,
                         cudaFuncAttributeMaxDynamicSharedMemorySize, SM_BYTES);
    attn_layer_kernel<<<nb, 256, SM_BYTES>>>(query, fact, mask, W1, b1, W2, b2, W3, b3, out);
}

// round 5
// speedup vs baseline: 1.2822x; 1.2822x over previous
#include <cuda_runtime.h>
#include <cstdint>

#define T    200
#define D    64
#define H1D  80
#define H2D  40
#define TP   201   // padded T stride: 201 mod 32 = 9 -> conflict-free columns

#define NEG_BIG (-2147483648.0f)

// Shared memory layout (floats)
#define SM_FLOATS (64*TP + 80*TP + 40*TP + 64*80 + 80*40 + 64 + 80 + 40 + 40 + 200 + 520)
#define SM_BYTES  (SM_FLOATS * 4)

__device__ __forceinline__ float fsigmoid(float x) {
    return __fdividef(1.0f, 1.0f + __expf(-x));
}

// ---- packed f32x2 helpers ----
__device__ __forceinline__ unsigned long long pk2(float lo, float hi) {
    unsigned long long r;
    asm("mov.b64 %0, {%1, %2};"
        : "=l"(r) : "r"(__float_as_uint(lo)), "r"(__float_as_uint(hi)));
    return r;
}
__device__ __forceinline__ void upk2(unsigned long long v, float& lo, float& hi) {
    unsigned int a, b;
    asm("mov.b64 {%0, %1}, %2;" : "=r"(a), "=r"(b) : "l"(v));
    lo = __uint_as_float(a);
    hi = __uint_as_float(b);
}
__device__ __forceinline__ void fma2(unsigned long long& d,
                                     unsigned long long a, unsigned long long b) {
    asm("fma.rn.f32x2 %0, %1, %2, %3;" : "=l"(d) : "l"(a), "l"(b), "l"(d));
}

__global__ __launch_bounds__(512, 1)
void attn_layer_kernel(const float* __restrict__ query,
                       const float* __restrict__ fact,
                       const int*   __restrict__ mask,
                       const float* __restrict__ W1,
                       const float* __restrict__ b1,
                       const float* __restrict__ W2,
                       const float* __restrict__ b2,
                       const float* __restrict__ W3,
                       const float* __restrict__ b3,
                       float* __restrict__ out)
{
    extern __shared__ float sm[];
    float* f_t = sm;                    // [64][TP]
    float* h1t = f_t + 64 * TP;         // [80][TP]
    float* h2t = h1t + 80 * TP;         // [40][TP]
    float* Wb  = h2t + 40 * TP;         // [64][80]   (16B aligned)
    float* W2s = Wb  + 64 * 80;         // [80][40]   (16B aligned)
    float* qs  = W2s + 80 * 40;         // [64]
    float* bb  = qs  + 64;              // [80]
    float* b2s = bb  + 80;              // [40]
    float* W3s = b2s + 40;              // [40]
    float* wts = W3s + 40;              // [200]
    float* red = wts + 200;             // [520] scratch / reductions

    const int b    = blockIdx.x;
    const int tid  = threadIdx.x;
    const int lane = tid & 31;
    const int wid  = tid >> 5;

    // ---- prefetch long-latency scalars ----
    int my_mask = 0;
    if (tid < T) my_mask = mask[(size_t)b * T + tid];
    const float b3v = b3[0];

    // ---- Stage 0: q + small constants ----
    if (tid < D) qs[tid] = query[b * D + tid];
    if (tid >= 64 && tid < 64 + H2D) {
        int k = tid - 64;
        b2s[k] = b2[k];
        W3s[k] = W3[k];
    }
    for (int i = tid; i < H1D * H2D; i += 512) W2s[i] = W2[i];
    __syncthreads();   // qs ready

    // ---- Stage 1: fact transpose + per-batch folded W1 ----
    const float* fb = fact + (size_t)b * T * D;
    for (int e = tid; e < T * D; e += 512) {
        int t = e >> 6, d = e & 63;
        f_t[d * TP + t] = fb[e];
    }
    // Wb[d][h] = (W1a - W1d)[d][h] + q[d]*W1c[d][h]
    for (int e = tid; e < D * H1D; e += 512) {
        int d = e / H1D, h = e - d * H1D;
        float a  = W1[d * H1D + h];
        float cc = W1[(128 + d) * H1D + h];
        float dd = W1[(192 + d) * H1D + h];
        Wb[e] = (a - dd) + qs[d] * cc;
    }
    // bias partials: bb[h] = b1[h] + sum_d q[d]*(W1b+W1d)[d][h]
    if (tid < 320) {
        const int h = tid % 80;
        const int c = tid / 80;            // 4 chunks of 16 d
        float s = 0.0f;
        #pragma unroll 4
        for (int d = c * 16; d < c * 16 + 16; d++)
            s += qs[d] * (W1[(64 + d) * H1D + h] + W1[(192 + d) * H1D + h]);
        red[c * 80 + h] = s;
    }
    __syncthreads();
    if (tid < H1D)
        bb[tid] = b1[tid] + red[tid] + red[80 + tid] + red[160 + tid] + red[240 + tid];
    __syncthreads();

    // ---- Stage 2: GEMM1  h1[t][h] = sigmoid(f[t,:] @ Wb[:,h] + bb[h]) ----
    // 500 threads: hg = tid/50 (h block of 8), tg = tid%50 (t = tg + 50*i).
    // Warp-uniform weight addresses (broadcast LDS.128), stride-1 activation LDS.
    // f32x2 pairs along h: acc2[i][jj] = {h=hg*8+2jj, h=hg*8+2jj+1} at t=tg+50i.
    if (tid < 500) {
        const int hg = tid / 50;
        const int tg = tid % 50;
        unsigned long long acc2[4][4];
        const unsigned long long z = pk2(0.0f, 0.0f);
        #pragma unroll
        for (int i = 0; i < 4; i++)
            #pragma unroll
            for (int jj = 0; jj < 4; jj++) acc2[i][jj] = z;

        #pragma unroll 4
        for (int d = 0; d < D; d++) {
            const ulonglong2* wv = (const ulonglong2*)(Wb + d * H1D + hg * 8);
            ulonglong2 w01 = wv[0];      // {h0,h1},{h2,h3}
            ulonglong2 w23 = wv[1];      // {h4,h5},{h6,h7}
            unsigned long long rf2[4];
            #pragma unroll
            for (int i = 0; i < 4; i++) {
                float f = f_t[d * TP + tg + 50 * i];
                rf2[i] = pk2(f, f);
            }
            #pragma unroll
            for (int i = 0; i < 4; i++) {
                fma2(acc2[i][0], rf2[i], w01.x);
                fma2(acc2[i][1], rf2[i], w01.y);
                fma2(acc2[i][2], rf2[i], w23.x);
                fma2(acc2[i][3], rf2[i], w23.y);
            }
        }
        #pragma unroll
        for (int jj = 0; jj < 4; jj++) {
            const int h0 = hg * 8 + 2 * jj;
            const float bi0 = bb[h0], bi1 = bb[h0 + 1];
            #pragma unroll
            for (int i = 0; i < 4; i++) {
                float a0, a1;
                upk2(acc2[i][jj], a0, a1);
                const int t = tg + 50 * i;
                h1t[h0 * TP + t]       = fsigmoid(a0 + bi0);
                h1t[(h0 + 1) * TP + t] = fsigmoid(a1 + bi1);
            }
        }
    }
    __syncthreads();

    // ---- Stage 3: GEMM2  h2[t][k] = sigmoid(h1[t,:] @ W2[:,k] + b2[k]) ----
    // 500 threads: kg = tid/50 (k block of 4), tg = tid%50.
    if (tid < 500) {
        const int kg = tid / 50;
        const int tg = tid % 50;
        unsigned long long acc2[4][2];
        const unsigned long long z = pk2(0.0f, 0.0f);
        #pragma unroll
        for (int i = 0; i < 4; i++) {
            acc2[i][0] = z; acc2[i][1] = z;
        }

        #pragma unroll 4
        for (int h = 0; h < H1D; h++) {
            ulonglong2 w = ((const ulonglong2*)(W2s + h * H2D))[kg];  // {k0,k1},{k2,k3}
            unsigned long long rh2[4];
            #pragma unroll
            for (int i = 0; i < 4; i++) {
                float v = h1t[h * TP + tg + 50 * i];
                rh2[i] = pk2(v, v);
            }
            #pragma unroll
            for (int i = 0; i < 4; i++) {
                fma2(acc2[i][0], rh2[i], w.x);
                fma2(acc2[i][1], rh2[i], w.y);
            }
        }
        #pragma unroll
        for (int jj = 0; jj < 2; jj++) {
            const int k0 = kg * 4 + 2 * jj;
            const float bi0 = b2s[k0], bi1 = b2s[k0 + 1];
            #pragma unroll
            for (int i = 0; i < 4; i++) {
                float a0, a1;
                upk2(acc2[i][jj], a0, a1);
                const int t = tg + 50 * i;
                h2t[k0 * TP + t]       = fsigmoid(a0 + bi0);
                h2t[(k0 + 1) * TP + t] = fsigmoid(a1 + bi1);
            }
        }
    }
    __syncthreads();

    // ---- Stage 4: scores + masked softmax ----
    float sc = NEG_BIG;
    float maskf = 0.0f;
    if (tid < T) {
        float s = b3v;
        #pragma unroll 8
        for (int k = 0; k < H2D; k++)
            s = fmaf(h2t[k * TP + tid], W3s[k], s);
        maskf = (float)my_mask;
        sc = (my_mask == 1) ? s : NEG_BIG;
    }
    float m = sc;
    #pragma unroll
    for (int o = 16; o; o >>= 1) m = fmaxf(m, __shfl_xor_sync(0xffffffffu, m, o));
    if (lane == 0) red[wid] = m;
    __syncthreads();
    if (tid == 0) {
        float mm = red[0];
        #pragma unroll
        for (int i = 1; i < 16; i++) mm = fmaxf(mm, red[i]);
        red[512] = mm;
    }
    __syncthreads();
    const float rowmax = red[512];

    float e = 0.0f;
    if (tid < T) e = __expf(sc - rowmax);
    float s2 = e;
    #pragma unroll
    for (int o = 16; o; o >>= 1) s2 += __shfl_xor_sync(0xffffffffu, s2, o);
    if (lane == 0) red[wid] = s2;
    __syncthreads();
    if (tid == 0) {
        float ss = 0.0f;
        #pragma unroll
        for (int i = 0; i < 16; i++) ss += red[i];
        red[513] = ss;
    }
    __syncthreads();
    const float inv_sum = __fdividef(1.0f, red[513]);
    if (tid < T) wts[tid] = e * maskf * inv_sum;
    __syncthreads();

    // ---- Stage 5: out[b][d] = sum_t wts[t] * fact[t][d] ----
    {
        const int d = tid & 63;
        const int c = tid >> 6;        // 8 chunks of 25 t
        float s = 0.0f;
        const int t0 = c * 25;
        #pragma unroll 5
        for (int t = t0; t < t0 + 25; t++)
            s = fmaf(wts[t], f_t[d * TP + t], s);
        red[c * 64 + d] = s;
    }
    __syncthreads();
    if (tid < D) {
        float s = 0.0f;
        #pragma unroll
        for (int c = 0; c < 8; c++) s += red[c * 64 + tid];
        out[(size_t)b * D + tid] = s;
    }
}

extern "C" void kernel_launch(void* const* d_in, const int* in_sizes, int n_in,
                              void* d_out, int out_size)
{
    const float* query = (const float*)d_in[0];
    const float* fact  = (const float*)d_in[1];
    const int*   mask  = (const int*)  d_in[2];
    const float* W1    = (const float*)d_in[3];
    const float* b1    = (const float*)d_in[4];
    const float* W2    = (const float*)d_in[5];
    const float* b2    = (const float*)d_in[6];
    const float* W3    = (const float*)d_in[7];
    const float* b3    = (const float*)d_in[8];
    float* out = (float*)d_out;

    const int nb = in_sizes[0] / D;

    cudaFuncSetAttribute(attn_layer_kernel,
                         cudaFuncAttributeMaxDynamicSharedMemorySize, SM_BYTES);
    attn_layer_kernel<<<nb, 512, SM_BYTES>>>(query, fact, mask, W1, b1, W2, b2, W3, b3, out);
}

// round 7
// speedup vs baseline: 1.3932x; 1.0866x over previous
#include <cuda_runtime.h>
#include <cstdint>

#define T    200
#define D    64
#define H1D  80
#define H2D  40
#define TP   201   // padded T stride: 201 mod 32 = 9 -> conflict-free columns

#define NEG_BIG (-2147483648.0f)

// Shared memory layout (floats)
#define SM_FLOATS (64*TP + 80*TP + 40*TP + 64*80 + 80*40 + 64 + 80 + 40 + 40 + 200 + 680)
#define SM_BYTES  (SM_FLOATS * 4)

__device__ __forceinline__ float fsigmoid(float x) {
    return __fdividef(1.0f, 1.0f + __expf(-x));
}

// ---- packed f32x2 helpers ----
__device__ __forceinline__ unsigned long long pk2(float lo, float hi) {
    unsigned long long r;
    asm("mov.b64 %0, {%1, %2};"
        : "=l"(r) : "r"(__float_as_uint(lo)), "r"(__float_as_uint(hi)));
    return r;
}
__device__ __forceinline__ void upk2(unsigned long long v, float& lo, float& hi) {
    unsigned int a, b;
    asm("mov.b64 {%0, %1}, %2;" : "=r"(a), "=r"(b) : "l"(v));
    lo = __uint_as_float(a);
    hi = __uint_as_float(b);
}
__device__ __forceinline__ void fma2(unsigned long long& d,
                                     unsigned long long a, unsigned long long b) {
    asm("fma.rn.f32x2 %0, %1, %2, %3;" : "=l"(d) : "l"(a), "l"(b), "l"(d));
}

__global__ __launch_bounds__(1024, 1)
void attn_layer_kernel(const float* __restrict__ query,
                       const float* __restrict__ fact,
                       const int*   __restrict__ mask,
                       const float* __restrict__ W1,
                       const float* __restrict__ b1,
                       const float* __restrict__ W2,
                       const float* __restrict__ b2,
                       const float* __restrict__ W3,
                       const float* __restrict__ b3,
                       float* __restrict__ out)
{
    extern __shared__ float sm[];
    float* f_t = sm;                    // [64][TP]
    float* h1t = f_t + 64 * TP;         // [80][TP]
    float* h2t = h1t + 80 * TP;         // [40][TP]
    float* Wb  = h2t + 40 * TP;         // [64][80]   (16B aligned)
    float* W2s = Wb  + 64 * 80;         // [80][40]   (16B aligned)
    float* qs  = W2s + 80 * 40;         // [64]
    float* bb  = qs  + 64;              // [80]
    float* b2s = bb  + 80;              // [40]
    float* W3s = b2s + 40;              // [40]
    float* wts = W3s + 40;              // [200]
    float* red = wts + 200;             // [680] scratch / reductions

    const int b    = blockIdx.x;
    const int tid  = threadIdx.x;
    const int lane = tid & 31;
    const int wid  = tid >> 5;

    // ---- prefetch long-latency scalars ----
    int my_mask = 0;
    if (tid < T) my_mask = mask[(size_t)b * T + tid];
    const float b3v = b3[0];

    // ---- Stage 0: q + small constants ----
    if (tid < D) qs[tid] = query[b * D + tid];
    if (tid >= 64 && tid < 64 + H2D) {
        int k = tid - 64;
        b2s[k] = b2[k];
        W3s[k] = W3[k];
    }
    for (int i = tid; i < H1D * H2D; i += 1024) W2s[i] = W2[i];
    __syncthreads();   // qs ready

    // ---- Stage 1: fact transpose (vectorized LDG.128) + folded W1 ----
    const float4* fb4 = (const float4*)(fact + (size_t)b * T * D);
    for (int v = tid; v < T * D / 4; v += 1024) {
        float4 x = fb4[v];
        int t  = v >> 4;            // v / 16  (16 float4 per row of 64)
        int d0 = (v & 15) * 4;
        f_t[(d0 + 0) * TP + t] = x.x;
        f_t[(d0 + 1) * TP + t] = x.y;
        f_t[(d0 + 2) * TP + t] = x.z;
        f_t[(d0 + 3) * TP + t] = x.w;
    }
    // Wb[d][h] = (W1a - W1d)[d][h] + q[d]*W1c[d][h]
    for (int e = tid; e < D * H1D; e += 1024) {
        int d = e / H1D, h = e - d * H1D;
        float a  = W1[d * H1D + h];
        float cc = W1[(128 + d) * H1D + h];
        float dd = W1[(192 + d) * H1D + h];
        Wb[e] = (a - dd) + qs[d] * cc;
    }
    // bias partials: bb[h] = b1[h] + sum_d q[d]*(W1b+W1d)[d][h]  (640 threads)
    if (tid < 640) {
        const int h = tid % 80;
        const int c = tid / 80;            // 8 chunks of 8 d
        float s = 0.0f;
        #pragma unroll 4
        for (int d = c * 8; d < c * 8 + 8; d++)
            s += qs[d] * (W1[(64 + d) * H1D + h] + W1[(192 + d) * H1D + h]);
        red[c * 80 + h] = s;
    }
    __syncthreads();
    if (tid < H1D) {
        float s = b1[tid];
        #pragma unroll
        for (int c = 0; c < 8; c++) s += red[c * 80 + tid];
        bb[tid] = s;
    }
    __syncthreads();

    // ---- Stage 2: GEMM1  h1[t][h] = sigmoid(f[t,:] @ Wb[:,h] + bb[h]) ----
    // 1000 threads: hg = tid/100 (h block of 8), tg = tid%100, t = tg + 100*i (i<2).
    // Weight LDS.128 (near-uniform broadcast), activation stride-1, f32x2 pairs on h.
    if (tid < 1000) {
        const int hg = tid / 100;
        const int tg = tid % 100;
        unsigned long long acc2[2][4];
        const unsigned long long z = pk2(0.0f, 0.0f);
        #pragma unroll
        for (int i = 0; i < 2; i++)
            #pragma unroll
            for (int jj = 0; jj < 4; jj++) acc2[i][jj] = z;

        #pragma unroll 4
        for (int d = 0; d < D; d++) {
            const ulonglong2* wv = (const ulonglong2*)(Wb + d * H1D + hg * 8);
            ulonglong2 w01 = wv[0];      // {h0,h1},{h2,h3}
            ulonglong2 w23 = wv[1];      // {h4,h5},{h6,h7}
            unsigned long long rf2[2];
            #pragma unroll
            for (int i = 0; i < 2; i++) {
                float f = f_t[d * TP + tg + 100 * i];
                rf2[i] = pk2(f, f);
            }
            #pragma unroll
            for (int i = 0; i < 2; i++) {
                fma2(acc2[i][0], rf2[i], w01.x);
                fma2(acc2[i][1], rf2[i], w01.y);
                fma2(acc2[i][2], rf2[i], w23.x);
                fma2(acc2[i][3], rf2[i], w23.y);
            }
        }
        #pragma unroll
        for (int jj = 0; jj < 4; jj++) {
            const int h0 = hg * 8 + 2 * jj;
            const float bi0 = bb[h0], bi1 = bb[h0 + 1];
            #pragma unroll
            for (int i = 0; i < 2; i++) {
                float a0, a1;
                upk2(acc2[i][jj], a0, a1);
                const int t = tg + 100 * i;
                h1t[h0 * TP + t]       = fsigmoid(a0 + bi0);
                h1t[(h0 + 1) * TP + t] = fsigmoid(a1 + bi1);
            }
        }
    }
    __syncthreads();

    // ---- Stage 3: GEMM2  h2[t][k] = sigmoid(h1[t,:] @ W2[:,k] + b2[k]) ----
    // 1000 threads: kg = tid/100 (k block of 4), tg = tid%100, t = tg + 100*i.
    if (tid < 1000) {
        const int kg = tid / 100;
        const int tg = tid % 100;
        unsigned long long acc2[2][2];
        const unsigned long long z = pk2(0.0f, 0.0f);
        acc2[0][0] = z; acc2[0][1] = z; acc2[1][0] = z; acc2[1][1] = z;

        #pragma unroll 4
        for (int h = 0; h < H1D; h++) {
            ulonglong2 w = ((const ulonglong2*)(W2s + h * H2D))[kg];  // {k0,k1},{k2,k3}
            unsigned long long rh2[2];
            #pragma unroll
            for (int i = 0; i < 2; i++) {
                float v = h1t[h * TP + tg + 100 * i];
                rh2[i] = pk2(v, v);
            }
            #pragma unroll
            for (int i = 0; i < 2; i++) {
                fma2(acc2[i][0], rh2[i], w.x);
                fma2(acc2[i][1], rh2[i], w.y);
            }
        }
        #pragma unroll
        for (int jj = 0; jj < 2; jj++) {
            const int k0 = kg * 4 + 2 * jj;
            const float bi0 = b2s[k0], bi1 = b2s[k0 + 1];
            #pragma unroll
            for (int i = 0; i < 2; i++) {
                float a0, a1;
                upk2(acc2[i][jj], a0, a1);
                const int t = tg + 100 * i;
                h2t[k0 * TP + t]       = fsigmoid(a0 + bi0);
                h2t[(k0 + 1) * TP + t] = fsigmoid(a1 + bi1);
            }
        }
    }
    __syncthreads();

    // ---- Stage 4: scores + masked softmax ----
    float sc = NEG_BIG;
    float maskf = 0.0f;
    if (tid < T) {
        float s = b3v;
        #pragma unroll 8
        for (int k = 0; k < H2D; k++)
            s = fmaf(h2t[k * TP + tid], W3s[k], s);
        maskf = (float)my_mask;
        sc = (my_mask == 1) ? s : NEG_BIG;
    }
    float m = sc;
    #pragma unroll
    for (int o = 16; o; o >>= 1) m = fmaxf(m, __shfl_xor_sync(0xffffffffu, m, o));
    if (lane == 0) red[wid] = m;
    __syncthreads();
    if (tid == 0) {
        float mm = red[0];
        #pragma unroll
        for (int i = 1; i < 32; i++) mm = fmaxf(mm, red[i]);
        red[512] = mm;
    }
    __syncthreads();
    const float rowmax = red[512];

    float e = 0.0f;
    if (tid < T) e = __expf(sc - rowmax);
    float s2 = e;
    #pragma unroll
    for (int o = 16; o; o >>= 1) s2 += __shfl_xor_sync(0xffffffffu, s2, o);
    if (lane == 0) red[wid] = s2;
    __syncthreads();
    if (tid == 0) {
        float ss = 0.0f;
        #pragma unroll
        for (int i = 0; i < 32; i++) ss += red[i];
        red[513] = ss;
    }
    __syncthreads();
    const float inv_sum = __fdividef(1.0f, red[513]);
    if (tid < T) wts[tid] = e * maskf * inv_sum;
    __syncthreads();

    // ---- Stage 5: out[b][d] = sum_t wts[t] * fact[t][d] ----
    if (tid < 512) {
        const int d = tid & 63;
        const int c = tid >> 6;        // 8 chunks of 25 t
        float s = 0.0f;
        const int t0 = c * 25;
        #pragma unroll 5
        for (int t = t0; t < t0 + 25; t++)
            s = fmaf(wts[t], f_t[d * TP + t], s);
        red[c * 64 + d] = s;
    }
    __syncthreads();
    if (tid < D) {
        float s = 0.0f;
        #pragma unroll
        for (int c = 0; c < 8; c++) s += red[c * 64 + tid];
        out[(size_t)b * D + tid] = s;
    }
}

extern "C" void kernel_launch(void* const* d_in, const int* in_sizes, int n_in,
                              void* d_out, int out_size)
{
    const float* query = (const float*)d_in[0];
    const float* fact  = (const float*)d_in[1];
    const int*   mask  = (const int*)  d_in[2];
    const float* W1    = (const float*)d_in[3];
    const float* b1    = (const float*)d_in[4];
    const float* W2    = (const float*)d_in[5];
    const float* b2    = (const float*)d_in[6];
    const float* W3    = (const float*)d_in[7];
    const float* b3    = (const float*)d_in[8];
    float* out = (float*)d_out;

    const int nb = in_sizes[0] / D;

    cudaFuncSetAttribute(attn_layer_kernel,
                         cudaFuncAttributeMaxDynamicSharedMemorySize, SM_BYTES);
    attn_layer_kernel<<<nb, 1024, SM_BYTES>>>(query, fact, mask, W1, b1, W2, b2, W3, b3, out);
}